// round 13
// baseline (speedup 1.0000x reference)
#include <cuda_runtime.h>
#include <cuda_bf16.h>
#include <cuda_fp16.h>
#include <math.h>
#include <stdint.h>

#define Bn 32
#define Tn 2048
#define Dn 512
#define Vn 1024
#define NT 65536          // Bn*Tn rows

// ---- output offsets (floats), tuple order flattened ----
#define O_GR     0
#define O_SUM    32
#define O_RMEAN  16416
#define O_RVAR   16448
#define O_COV    16480
#define O_MASK   16512
#define O_LOGDUR 82048
#define O_REF    147584
#define O_ATTN   213120
#define O_FIT    278656
#define O_NORM   344192

// ---- scratch (device globals; no runtime allocation) ----
__device__ __half g_x[(size_t)NT * Dn];    // 64 MB  conv1 input fp16
__device__ __half g_y[(size_t)NT * Dn];    // 64 MB  conv1 out fp16
__device__ __half g_h[(size_t)NT * Dn];    // 64 MB  conv2 out fp16
__device__ __half g_w1[(size_t)3 * Dn * Dn];  // conv1 weights fp16 [tap][o][c]
__device__ __half g_w2[(size_t)3 * Dn * Dn];  // conv2 weights fp16
__device__ float g_part[(size_t)(NT / 32) * 1024];  // 8 MB pool partials
__device__ float g_ref[NT];
__device__ float g_cat[Bn * 2 * Dn];
__device__ float g_g1[Bn * Dn];
__device__ float g_n[Bn];

__device__ __forceinline__ float gelu_exact(float x) {
    return 0.5f * x * (1.0f + erff(x * 0.70710678118654752440f));
}

__device__ __forceinline__ uint32_t smem_u32(const void* p) {
    uint32_t a;
    asm("{ .reg .u64 t; cvta.to.shared.u64 t, %1; cvt.u32.u64 %0, t; }" : "=r"(a) : "l"(p));
    return a;
}

__device__ __forceinline__ void ldsm4(uint32_t* r, uint32_t addr) {
    asm volatile("ldmatrix.sync.aligned.m8n8.x4.shared.b16 {%0,%1,%2,%3}, [%4];"
        : "=r"(r[0]), "=r"(r[1]), "=r"(r[2]), "=r"(r[3]) : "r"(addr));
}

__device__ __forceinline__ void mma16816(float* d, const uint32_t* a, const uint32_t* b) {
    asm volatile(
        "mma.sync.aligned.m16n8k16.row.col.f32.f16.f16.f32 "
        "{%0,%1,%2,%3}, {%4,%5,%6,%7}, {%8,%9}, {%0,%1,%2,%3};"
        : "+f"(d[0]), "+f"(d[1]), "+f"(d[2]), "+f"(d[3])
        : "r"(a[0]), "r"(a[1]), "r"(a[2]), "r"(a[3]), "r"(b[0]), "r"(b[1]));
}

__device__ __forceinline__ void cp16(uint32_t dst, const void* src, bool pred) {
    int sz = pred ? 16 : 0;
    asm volatile("cp.async.cg.shared.global [%0], [%1], 16, %2;"
        :: "r"(dst), "l"(src), "r"(sz) : "memory");
}
#define CP_COMMIT() asm volatile("cp.async.commit_group;" ::: "memory")

// works for blockDim.x multiple of 32, <= 1024
__device__ __forceinline__ float blkReduceSum(float v, float* red) {
    int tid = threadIdx.x;
    int lane = tid & 31, wid = tid >> 5;
    #pragma unroll
    for (int o = 16; o; o >>= 1) v += __shfl_xor_sync(0xffffffffu, v, o);
    if (lane == 0) red[wid] = v;
    __syncthreads();
    float r = 0.f;
    if (wid == 0) {
        int nw = blockDim.x >> 5;
        r = (lane < nw) ? red[lane] : 0.f;
        #pragma unroll
        for (int o = 16; o; o >>= 1) r += __shfl_xor_sync(0xffffffffu, r, o);
        if (lane == 0) red[0] = r;
    }
    __syncthreads();
    r = red[0];
    __syncthreads();
    return r;
}

// ============================================================================
// K0: per-batch stats (logdur, exact median via bitonic sort, residual stats)
// ============================================================================
__global__ __launch_bounds__(1024) void stats_kernel(
    const float* __restrict__ dur, const float* __restrict__ mask,
    float* __restrict__ out)
{
    __shared__ float s[Tn];
    __shared__ float red[32];
    int b = blockIdx.x;
    int tid = threadIdx.x;
    const float* durb = dur + b * Tn;
    const float* mb   = mask + b * Tn;

    float ldv[2], mval[2];
    int cnt = 0;
    #pragma unroll
    for (int p = 0; p < 2; p++) {
        int i = tid + p * 1024;
        float m = fminf(fmaxf(mb[i], 0.f), 1.f);
        float ld = logf(fmaxf(durb[i], 1e-4f)) * m;
        mval[p] = m;
        ldv[p] = ld;
        bool valid = m > 0.5f;
        s[i] = valid ? ld : __int_as_float(0x7f800000);
        if (valid) cnt++;
    }
    float n_f = blkReduceSum((float)cnt, red);
    int n = (int)(n_f + 0.5f);

    for (int k = 2; k <= Tn; k <<= 1) {
        for (int j = k >> 1; j > 0; j >>= 1) {
            #pragma unroll
            for (int p = 0; p < 2; p++) {
                int i = tid + p * 1024;
                int ixj = i ^ j;
                if (ixj > i) {
                    bool up = ((i & k) == 0);
                    float a = s[i], c = s[ixj];
                    bool swap = up ? (a > c) : (a < c);
                    if (swap) { s[i] = c; s[ixj] = a; }
                }
            }
            __syncthreads();
        }
    }

    float med = (n > 0) ? s[(n - 1) >> 1] : 0.f;
    float support = fmaxf(n_f, 1.f);

    float refv[2];
    float sum_ref = 0.f;
    #pragma unroll
    for (int p = 0; p < 2; p++) {
        float r = (ldv[p] - med) * mval[p];
        refv[p] = r;
        sum_ref += r * mval[p];
    }
    float tot = blkReduceSum(sum_ref, red);
    float rmean = tot / support;

    float sv = 0.f;
    #pragma unroll
    for (int p = 0; p < 2; p++) {
        float d = refv[p] - rmean;
        sv += d * d * mval[p];
    }
    float totv = blkReduceSum(sv, red);
    float rvar = fmaxf(totv / support, 1e-4f);

    #pragma unroll
    for (int p = 0; p < 2; p++) {
        int i = tid + p * 1024;
        int gi = b * Tn + i;
        out[O_MASK   + gi] = mval[p];
        out[O_LOGDUR + gi] = ldv[p];
        out[O_REF    + gi] = refv[p];
        out[O_ATTN   + gi] = mval[p] / support;
        out[O_FIT    + gi] = rmean * mval[p];
        g_ref[gi] = refv[p];
    }
    if (tid == 0) {
        out[O_GR    + b] = med;
        out[O_RMEAN + b] = rmean;
        out[O_RVAR  + b] = rvar;
        out[O_COV   + b] = fmaxf(n_f / (float)Tn, 0.05f);
        g_n[b] = n_f;
    }
}

// ============================================================================
// K1: embedding + residual projection -> fp16 (g_x)
// ============================================================================
__global__ __launch_bounds__(128) void embed_kernel(
    const int* __restrict__ ids, const float* __restrict__ emb,
    const float* __restrict__ auxw, const float* __restrict__ auxb)
{
    int row = blockIdx.x;
    int tid = threadIdx.x;
    int id = ids[row];
    float r = g_ref[row];
    float4 e = ((const float4*)(emb + (size_t)id * Dn))[tid];
    float4 w = ((const float4*)auxw)[tid];
    float4 bb = ((const float4*)auxb)[tid];
    __half h[4];
    h[0] = __float2half_rn(e.x + r * w.x + bb.x);
    h[1] = __float2half_rn(e.y + r * w.y + bb.y);
    h[2] = __float2half_rn(e.z + r * w.z + bb.z);
    h[3] = __float2half_rn(e.w + r * w.w + bb.w);
    *(ushort4*)(g_x + (size_t)row * Dn + tid * 4) = *(ushort4*)h;
}

// ============================================================================
// K2: weight prep for BOTH convs: Wt[k][o][c] = w[o][c][k] in fp16
// ============================================================================
__global__ __launch_bounds__(256) void prep_w_kernel(
    const float* __restrict__ w1, const float* __restrict__ w2)
{
    int idx = blockIdx.x * 256 + threadIdx.x;   // over 2 * 786432
    int half_sel = idx >= (3 * Dn * Dn);
    int i = idx - half_sel * (3 * Dn * Dn);
    int j = i >> 9;           // tap*512 + o
    int c = i & 511;
    int k = j >> 9;
    int o = j & 511;
    const float* w = half_sel ? w2 : w1;
    __half v = __float2half_rn(w[((size_t)o * Dn + c) * 3 + k]);
    if (half_sel) g_w2[i] = v;
    else          g_w1[i] = v;
}

// ============================================================================
// K3: causal conv via mma.sync fp16 (R11 config: 256 thr, 2 CTAs/SM,
// warp tile 32x64 (4m x 2n), CTA tile 128x128, K-chunk 64, X cp.async
// double-buffered, W sync-loaded).
// ============================================================================
#define PX 144                       // smem row pitch (bytes): 128B data + 16 pad
#define XSTAGE (130 * PX)            // 18720
#define S_X0 0
#define S_X1 XSTAGE
#define S_W  (2 * XSTAGE)            // 37440
#define CONV_SMEM (S_W + 3 * 128 * PX)  // 92736
#define NCHUNK 8

template<int SRC, int MODE>
__global__ __launch_bounds__(256, 2) void conv_mma_kernel(const float* __restrict__ bias)
{
    extern __shared__ char sm[];
    const __half* __restrict__ x = (SRC == 0) ? g_x : g_y;
    const __half* __restrict__ wsel = (SRC == 0) ? g_w1 : g_w2;

    uint32_t sb = smem_u32(sm);
    int tid = threadIdx.x;
    int lane = tid & 31, wid = tid >> 5;
    int wm = wid & 3;              // 0..3, 32 rows each
    int wn = wid >> 2;             // 0..1, 64 cols each

    int N0 = blockIdx.x * 128;     // output-channel tile
    int tile = blockIdx.y;         // global row tile (128 rows)
    int b  = tile >> 4;
    int T0 = (tile & 15) << 7;

    float acc[2][8][4];
    #pragma unroll
    for (int mt = 0; mt < 2; mt++)
        #pragma unroll
        for (int nt = 0; nt < 8; nt++)
            #pragma unroll
            for (int q = 0; q < 4; q++) acc[mt][nt][q] = 0.f;

    auto issueX = [&](int ck, uint32_t stoff) {
        int c0 = ck * 64;
        #pragma unroll
        for (int l = 0; l < 5; l++) {
            int i = tid + l * 256;
            if (l < 4 || i < 1040) {
                int row = i >> 3, q = i & 7;
                int t = T0 - 2 + row;
                bool ok = (t >= 0);
                size_t g = ((size_t)(b * Tn + (ok ? t : 0))) * Dn + c0 + q * 8;
                cp16(sb + stoff + row * PX + q * 16, x + g, ok);
            }
        }
        CP_COMMIT();
    };

    issueX(0, S_X0);

    for (int ck = 0; ck < NCHUNK; ck++) {
        if (ck) __syncthreads();     // prev compute done: W + other X buffer free
        if (ck + 1 < NCHUNK) issueX(ck + 1, ((ck + 1) & 1) ? S_X1 : S_X0);

        // ---- W tile (sync): 3 taps x 128 o x 64 ch ----
        int c0 = ck * 64;
        #pragma unroll
        for (int l = 0; l < 12; l++) {
            int i = tid + l * 256;
            int row = i >> 3, q = i & 7;       // row 0..383
            int tap = row >> 7, o = row & 127;
            size_t g = ((size_t)(tap * Dn + N0 + o)) * Dn + c0 + q * 8;
            *(uint4*)(sm + S_W + tap * (128 * PX) + o * PX + q * 16) =
                *(const uint4*)(wsel + g);
        }
        if (ck + 1 < NCHUNK) asm volatile("cp.async.wait_group 1;" ::: "memory");
        else                 asm volatile("cp.async.wait_group 0;" ::: "memory");
        __syncthreads();

        uint32_t xbase = sb + ((ck & 1) ? S_X1 : S_X0);
        #pragma unroll
        for (int k16 = 0; k16 < 4; k16++) {
            int kb = k16 * 32 + ((lane >> 4) << 4);
            #pragma unroll
            for (int tap = 0; tap < 3; tap++) {
                uint32_t aoff = (uint32_t)((wm * 32 + (lane & 15) + tap) * PX) + kb;
                uint32_t boff = (uint32_t)(tap * (128 * PX) + (wn * 64 + (lane & 15)) * PX) + kb;
                uint32_t a0[4], a1[4];
                ldsm4(a0, xbase + aoff);
                ldsm4(a1, xbase + aoff + 16 * PX);
                uint32_t bw[4][4];
                #pragma unroll
                for (int q = 0; q < 4; q++)
                    ldsm4(bw[q], sb + S_W + boff + q * (16 * PX));
                #pragma unroll
                for (int nt = 0; nt < 8; nt++) {
                    uint32_t b2[2] = { bw[nt >> 1][nt & 1], bw[nt >> 1][(nt & 1) + 2] };
                    mma16816(acc[0][nt], a0, b2);
                    mma16816(acc[1][nt], a1, b2);
                }
            }
        }
    }

    // ---- epilogue: + bias, exact GELU, store fp16 ----
    __half* __restrict__ yout = (MODE == 1) ? g_h : g_y;
    int col0 = N0 + wn * 64 + (lane & 3) * 2;
    #pragma unroll
    for (int mt = 0; mt < 2; mt++) {
        int r0 = tile * 128 + wm * 32 + mt * 16 + (lane >> 2);
        #pragma unroll
        for (int nt = 0; nt < 8; nt++) {
            int col = col0 + nt * 8;
            float2 bi = *(const float2*)&bias[col];
            #pragma unroll
            for (int h = 0; h < 2; h++) {
                int r = r0 + h * 8;
                float v0 = gelu_exact(acc[mt][nt][2 * h + 0] + bi.x);
                float v1 = gelu_exact(acc[mt][nt][2 * h + 1] + bi.y);
                __half2 p;
                p.x = __float2half_rn(v0);
                p.y = __float2half_rn(v1);
                *(__half2*)&yout[(size_t)r * Dn + col] = p;
            }
        }
    }
}

// ============================================================================
// K4: LayerNorm (+gamma/beta, *mask) fused with pooling partials.
// 32 rows per block: each warp accumulates 4 rows in registers, then one
// smem tree per block. Partials: 2048 blocks x 1024 floats = 8 MB.
// ============================================================================
__global__ __launch_bounds__(256) void ln_pool_kernel(
    const float* __restrict__ g, const float* __restrict__ bb,
    const float* __restrict__ mask)
{
    __shared__ float part[8][1024];   // 32 KB
    int wid = threadIdx.x >> 5;
    int lane = threadIdx.x & 31;

    float acc1[16], acc2[16];
    #pragma unroll
    for (int i = 0; i < 16; i++) { acc1[i] = 0.f; acc2[i] = 0.f; }

    #pragma unroll
    for (int rr = 0; rr < 4; rr++) {
        int row = blockIdx.x * 32 + wid * 4 + rr;
        const __half* xr = g_h + (size_t)row * Dn;

        float4 v[4];
        float sum = 0.f;
        #pragma unroll
        for (int p = 0; p < 4; p++) {
            int c = p * 32 + lane;
            uint2 raw = *(const uint2*)(xr + 4 * c);
            __half2 h0 = *(__half2*)&raw.x;
            __half2 h1 = *(__half2*)&raw.y;
            float2 f0 = __half22float2(h0);
            float2 f1 = __half22float2(h1);
            v[p] = make_float4(f0.x, f0.y, f1.x, f1.y);
            sum += v[p].x + v[p].y + v[p].z + v[p].w;
        }
        #pragma unroll
        for (int o = 16; o; o >>= 1) sum += __shfl_xor_sync(0xffffffffu, sum, o);
        float mean = sum * (1.0f / Dn);

        float s2 = 0.f;
        #pragma unroll
        for (int p = 0; p < 4; p++) {
            float dx = v[p].x - mean, dy = v[p].y - mean, dz = v[p].z - mean, dw = v[p].w - mean;
            s2 += dx * dx + dy * dy + dz * dz + dw * dw;
        }
        #pragma unroll
        for (int o = 16; o; o >>= 1) s2 += __shfl_xor_sync(0xffffffffu, s2, o);
        float rstd = rsqrtf(s2 * (1.0f / Dn) + 1e-5f);

        float m = fminf(fmaxf(mask[row], 0.f), 1.f);
        #pragma unroll
        for (int p = 0; p < 4; p++) {
            int c = p * 32 + lane;
            float4 gg = ((const float4*)g)[c];
            float4 bv = ((const float4*)bb)[c];
            float o0 = ((v[p].x - mean) * rstd * gg.x + bv.x) * m;
            float o1 = ((v[p].y - mean) * rstd * gg.y + bv.y) * m;
            float o2 = ((v[p].z - mean) * rstd * gg.z + bv.z) * m;
            float o3 = ((v[p].w - mean) * rstd * gg.w + bv.w) * m;
            acc1[p * 4 + 0] += o0;  acc2[p * 4 + 0] += o0 * o0;
            acc1[p * 4 + 1] += o1;  acc2[p * 4 + 1] += o1 * o1;
            acc1[p * 4 + 2] += o2;  acc2[p * 4 + 2] += o2 * o2;
            acc1[p * 4 + 3] += o3;  acc2[p * 4 + 3] += o3 * o3;
        }
    }

    #pragma unroll
    for (int p = 0; p < 4; p++) {
        int d = 4 * (p * 32 + lane);
        #pragma unroll
        for (int u = 0; u < 4; u++) {
            part[wid][d + u] = acc1[p * 4 + u];
            part[wid][512 + d + u] = acc2[p * 4 + u];
        }
    }
    __syncthreads();

    float* dst = g_part + (size_t)blockIdx.x * 1024;
    for (int i = threadIdx.x; i < 1024; i += 256) {
        float s = 0.f;
        #pragma unroll
        for (int w = 0; w < 8; w++) s += part[w][i];
        dst[i] = s;
    }
}

// ============================================================================
// K5: finalize pooling: reduce 64 partials per batch -> g_cat [B, 2D]
// ============================================================================
__global__ __launch_bounds__(128) void pool_finalize_kernel()
{
    int b = blockIdx.x;
    int d = blockIdx.y * 128 + threadIdx.x;   // 0..511
    const float* pb = g_part + (size_t)b * 64 * 1024;
    float sv = 0.f, sq = 0.f;
    #pragma unroll 4
    for (int s = 0; s < 64; s++) {
        sv += pb[(size_t)s * 1024 + d];
        sq += pb[(size_t)s * 1024 + 512 + d];
    }
    float n = g_n[b];
    float denom = fmaxf(n, 1.f);
    float mean = sv / denom;
    float diff2 = sq - 2.f * mean * sv + mean * mean * n;
    float sd = sqrtf(fmaxf(diff2, 0.f) / denom + 1e-6f);
    g_cat[b * 2 * Dn + d] = mean;
    g_cat[b * 2 * Dn + Dn + d] = sd;
}

// ============================================================================
// K6: p1 (1024 -> 512) + gelu -> g_g1  (one block per batch, 512 threads)
// ============================================================================
__global__ __launch_bounds__(512) void mlp1_kernel(
    const float* __restrict__ w, const float* __restrict__ bias)
{
    __shared__ float c[2 * Dn];
    int b = blockIdx.x;
    int j = threadIdx.x;
    for (int i = threadIdx.x; i < 2 * Dn; i += 512) c[i] = g_cat[b * 2 * Dn + i];
    __syncthreads();
    const float* wr = w + (size_t)j * (2 * Dn);
    float acc = bias[j];
    #pragma unroll 8
    for (int k = 0; k < 2 * Dn; k++) acc = fmaf(c[k], wr[k], acc);
    g_g1[b * Dn + j] = gelu_exact(acc);
}

// ============================================================================
// K7: p2 (512 -> 512) + tanh + guard + fused coeff_norm
// ============================================================================
__global__ __launch_bounds__(512) void mlp2_kernel(
    const float* __restrict__ w, const float* __restrict__ bias,
    float* __restrict__ out)
{
    __shared__ float c[Dn];
    __shared__ float red[32];
    int b = blockIdx.x;
    int j = threadIdx.x;
    if (j < Dn) c[j] = g_g1[b * Dn + j];
    __syncthreads();
    const float* wr = w + (size_t)j * Dn;
    float acc = bias[j];
    #pragma unroll 8
    for (int k = 0; k < Dn; k++) acc = fmaf(c[k], wr[k], acc);
    float v = tanhf(acc);
    if (g_n[b] <= 0.f) v = 0.f;
    out[O_SUM + b * Dn + j] = v;
    float tot = blkReduceSum(v * v, red);
    if (j == 0) out[O_NORM + b] = sqrtf(tot);
}

// ============================================================================
extern "C" void kernel_launch(void* const* d_in, const int* in_sizes, int n_in,
                              void* d_out, int out_size)
{
    const int*   ids  = (const int*)d_in[0];
    const float* dur  = (const float*)d_in[1];
    const float* mask = (const float*)d_in[2];
    const float* emb  = (const float*)d_in[3];
    const float* auxw = (const float*)d_in[4];
    const float* auxb = (const float*)d_in[5];
    const float* c1w  = (const float*)d_in[6];
    const float* c1b  = (const float*)d_in[7];
    const float* c2w  = (const float*)d_in[8];
    const float* c2b  = (const float*)d_in[9];
    const float* lng  = (const float*)d_in[10];
    const float* lnb  = (const float*)d_in[11];
    const float* p1w  = (const float*)d_in[12];
    const float* p1b  = (const float*)d_in[13];
    const float* p2w  = (const float*)d_in[14];
    const float* p2b  = (const float*)d_in[15];
    float* out = (float*)d_out;

    cudaFuncSetAttribute(conv_mma_kernel<0, 0>,
                         cudaFuncAttributeMaxDynamicSharedMemorySize, CONV_SMEM);
    cudaFuncSetAttribute(conv_mma_kernel<1, 1>,
                         cudaFuncAttributeMaxDynamicSharedMemorySize, CONV_SMEM);

    stats_kernel<<<Bn, 1024>>>(dur, mask, out);
    prep_w_kernel<<<(2 * 3 * Dn * Dn) / 256, 256>>>(c1w, c2w);
    embed_kernel<<<NT, 128>>>(ids, emb, auxw, auxb);

    dim3 cg(Dn / 128, NT / 128);   // (4, 512)
    conv_mma_kernel<0, 0><<<cg, 256, CONV_SMEM>>>(c1b);
    conv_mma_kernel<1, 1><<<cg, 256, CONV_SMEM>>>(c2b);

    ln_pool_kernel<<<NT / 32, 256>>>(lng, lnb, mask);

    dim3 pf(Bn, Dn / 128);         // (32, 4)
    pool_finalize_kernel<<<pf, 128>>>();

    mlp1_kernel<<<Bn, 512>>>(p1w, p1b);
    mlp2_kernel<<<Bn, 512>>>(p2w, p2b, out);
}

// round 15
// speedup vs baseline: 1.2718x; 1.2718x over previous
#include <cuda_runtime.h>
#include <cuda_bf16.h>
#include <cuda_fp16.h>
#include <math.h>
#include <stdint.h>

#define Bn 32
#define Tn 2048
#define Dn 512
#define Vn 1024
#define NT 65536          // Bn*Tn rows

// ---- output offsets (floats), tuple order flattened ----
#define O_GR     0
#define O_SUM    32
#define O_RMEAN  16416
#define O_RVAR   16448
#define O_COV    16480
#define O_MASK   16512
#define O_LOGDUR 82048
#define O_REF    147584
#define O_ATTN   213120
#define O_FIT    278656
#define O_NORM   344192

// ---- scratch (device globals; no runtime allocation) ----
__device__ __half g_x[(size_t)NT * Dn];    // 64 MB  conv1 input fp16
__device__ __half g_y[(size_t)NT * Dn];    // 64 MB  conv1 out fp16
__device__ __half g_h[(size_t)NT * Dn];    // 64 MB  conv2 out fp16
__device__ __half g_w1[(size_t)3 * Dn * Dn];  // conv1 weights fp16 [tap][o][c]
__device__ __half g_w2[(size_t)3 * Dn * Dn];  // conv2 weights fp16
__device__ float g_part[(size_t)(NT / 8) * 1024];  // 32 MB pool partials
__device__ float g_ref[NT];
__device__ float g_cat[Bn * 2 * Dn];
__device__ float g_g1[Bn * Dn];
__device__ float g_n[Bn];

__device__ __forceinline__ float gelu_exact(float x) {
    return 0.5f * x * (1.0f + erff(x * 0.70710678118654752440f));
}

__device__ __forceinline__ uint32_t smem_u32(const void* p) {
    uint32_t a;
    asm("{ .reg .u64 t; cvta.to.shared.u64 t, %1; cvt.u32.u64 %0, t; }" : "=r"(a) : "l"(p));
    return a;
}

__device__ __forceinline__ void ldsm4(uint32_t* r, uint32_t addr) {
    asm volatile("ldmatrix.sync.aligned.m8n8.x4.shared.b16 {%0,%1,%2,%3}, [%4];"
        : "=r"(r[0]), "=r"(r[1]), "=r"(r[2]), "=r"(r[3]) : "r"(addr));
}

__device__ __forceinline__ void mma16816(float* d, const uint32_t* a, const uint32_t* b) {
    asm volatile(
        "mma.sync.aligned.m16n8k16.row.col.f32.f16.f16.f32 "
        "{%0,%1,%2,%3}, {%4,%5,%6,%7}, {%8,%9}, {%0,%1,%2,%3};"
        : "+f"(d[0]), "+f"(d[1]), "+f"(d[2]), "+f"(d[3])
        : "r"(a[0]), "r"(a[1]), "r"(a[2]), "r"(a[3]), "r"(b[0]), "r"(b[1]));
}

__device__ __forceinline__ void cp16(uint32_t dst, const void* src, bool pred) {
    int sz = pred ? 16 : 0;
    asm volatile("cp.async.cg.shared.global [%0], [%1], 16, %2;"
        :: "r"(dst), "l"(src), "r"(sz) : "memory");
}
#define CP_COMMIT() asm volatile("cp.async.commit_group;" ::: "memory")

// works for blockDim.x multiple of 32, <= 1024
__device__ __forceinline__ float blkReduceSum(float v, float* red) {
    int tid = threadIdx.x;
    int lane = tid & 31, wid = tid >> 5;
    #pragma unroll
    for (int o = 16; o; o >>= 1) v += __shfl_xor_sync(0xffffffffu, v, o);
    if (lane == 0) red[wid] = v;
    __syncthreads();
    float r = 0.f;
    if (wid == 0) {
        int nw = blockDim.x >> 5;
        r = (lane < nw) ? red[lane] : 0.f;
        #pragma unroll
        for (int o = 16; o; o >>= 1) r += __shfl_xor_sync(0xffffffffu, r, o);
        if (lane == 0) red[0] = r;
    }
    __syncthreads();
    r = red[0];
    __syncthreads();
    return r;
}

// ============================================================================
// K0: per-batch stats (logdur, exact median via bitonic sort, residual stats)
// Full __syncthreads in every bitonic phase (deterministic; do not relax).
// ============================================================================
__global__ __launch_bounds__(1024) void stats_kernel(
    const float* __restrict__ dur, const float* __restrict__ mask,
    float* __restrict__ out)
{
    __shared__ float s[Tn];
    __shared__ float red[32];
    int b = blockIdx.x;
    int tid = threadIdx.x;
    const float* durb = dur + b * Tn;
    const float* mb   = mask + b * Tn;

    float ldv[2], mval[2];
    int cnt = 0;
    #pragma unroll
    for (int p = 0; p < 2; p++) {
        int i = tid + p * 1024;
        float m = fminf(fmaxf(mb[i], 0.f), 1.f);
        float ld = logf(fmaxf(durb[i], 1e-4f)) * m;
        mval[p] = m;
        ldv[p] = ld;
        bool valid = m > 0.5f;
        s[i] = valid ? ld : __int_as_float(0x7f800000);
        if (valid) cnt++;
    }
    float n_f = blkReduceSum((float)cnt, red);
    int n = (int)(n_f + 0.5f);

    for (int k = 2; k <= Tn; k <<= 1) {
        for (int j = k >> 1; j > 0; j >>= 1) {
            #pragma unroll
            for (int p = 0; p < 2; p++) {
                int i = tid + p * 1024;
                int ixj = i ^ j;
                if (ixj > i) {
                    bool up = ((i & k) == 0);
                    float a = s[i], c = s[ixj];
                    bool swap = up ? (a > c) : (a < c);
                    if (swap) { s[i] = c; s[ixj] = a; }
                }
            }
            __syncthreads();
        }
    }

    float med = (n > 0) ? s[(n - 1) >> 1] : 0.f;
    float support = fmaxf(n_f, 1.f);

    float refv[2];
    float sum_ref = 0.f;
    #pragma unroll
    for (int p = 0; p < 2; p++) {
        float r = (ldv[p] - med) * mval[p];
        refv[p] = r;
        sum_ref += r * mval[p];
    }
    float tot = blkReduceSum(sum_ref, red);
    float rmean = tot / support;

    float sv = 0.f;
    #pragma unroll
    for (int p = 0; p < 2; p++) {
        float d = refv[p] - rmean;
        sv += d * d * mval[p];
    }
    float totv = blkReduceSum(sv, red);
    float rvar = fmaxf(totv / support, 1e-4f);

    #pragma unroll
    for (int p = 0; p < 2; p++) {
        int i = tid + p * 1024;
        int gi = b * Tn + i;
        out[O_MASK   + gi] = mval[p];
        out[O_LOGDUR + gi] = ldv[p];
        out[O_REF    + gi] = refv[p];
        out[O_ATTN   + gi] = mval[p] / support;
        out[O_FIT    + gi] = rmean * mval[p];
        g_ref[gi] = refv[p];
    }
    if (tid == 0) {
        out[O_GR    + b] = med;
        out[O_RMEAN + b] = rmean;
        out[O_RVAR  + b] = rvar;
        out[O_COV   + b] = fmaxf(n_f / (float)Tn, 0.05f);
        g_n[b] = n_f;
    }
}

// ============================================================================
// K1: embedding + residual projection -> fp16 (g_x)
// ============================================================================
__global__ __launch_bounds__(128) void embed_kernel(
    const int* __restrict__ ids, const float* __restrict__ emb,
    const float* __restrict__ auxw, const float* __restrict__ auxb)
{
    int row = blockIdx.x;
    int tid = threadIdx.x;
    int id = ids[row];
    float r = g_ref[row];
    float4 e = ((const float4*)(emb + (size_t)id * Dn))[tid];
    float4 w = ((const float4*)auxw)[tid];
    float4 bb = ((const float4*)auxb)[tid];
    __half h[4];
    h[0] = __float2half_rn(e.x + r * w.x + bb.x);
    h[1] = __float2half_rn(e.y + r * w.y + bb.y);
    h[2] = __float2half_rn(e.z + r * w.z + bb.z);
    h[3] = __float2half_rn(e.w + r * w.w + bb.w);
    *(ushort4*)(g_x + (size_t)row * Dn + tid * 4) = *(ushort4*)h;
}

// ============================================================================
// K2: weight prep for BOTH convs: Wt[k][o][c] = w[o][c][k] in fp16
// ============================================================================
__global__ __launch_bounds__(256) void prep_w_kernel(
    const float* __restrict__ w1, const float* __restrict__ w2)
{
    int idx = blockIdx.x * 256 + threadIdx.x;   // over 2 * 786432
    int half_sel = idx >= (3 * Dn * Dn);
    int i = idx - half_sel * (3 * Dn * Dn);
    int j = i >> 9;           // tap*512 + o
    int c = i & 511;
    int k = j >> 9;
    int o = j & 511;
    const float* w = half_sel ? w2 : w1;
    __half v = __float2half_rn(w[((size_t)o * Dn + c) * 3 + k]);
    if (half_sel) g_w2[i] = v;
    else          g_w1[i] = v;
}

// ============================================================================
// K3: causal conv via mma.sync fp16 (R11 config: 256 thr, 2 CTAs/SM,
// warp tile 32x64 (4m x 2n), CTA tile 128x128, K-chunk 64, X cp.async
// double-buffered, W sync-loaded).
// ============================================================================
#define PX 144                       // smem row pitch (bytes): 128B data + 16 pad
#define XSTAGE (130 * PX)            // 18720
#define S_X0 0
#define S_X1 XSTAGE
#define S_W  (2 * XSTAGE)            // 37440
#define CONV_SMEM (S_W + 3 * 128 * PX)  // 92736
#define NCHUNK 8

template<int SRC, int MODE>
__global__ __launch_bounds__(256, 2) void conv_mma_kernel(const float* __restrict__ bias)
{
    extern __shared__ char sm[];
    const __half* __restrict__ x = (SRC == 0) ? g_x : g_y;
    const __half* __restrict__ wsel = (SRC == 0) ? g_w1 : g_w2;

    uint32_t sb = smem_u32(sm);
    int tid = threadIdx.x;
    int lane = tid & 31, wid = tid >> 5;
    int wm = wid & 3;              // 0..3, 32 rows each
    int wn = wid >> 2;             // 0..1, 64 cols each

    int N0 = blockIdx.x * 128;     // output-channel tile
    int tile = blockIdx.y;         // global row tile (128 rows)
    int b  = tile >> 4;
    int T0 = (tile & 15) << 7;

    float acc[2][8][4];
    #pragma unroll
    for (int mt = 0; mt < 2; mt++)
        #pragma unroll
        for (int nt = 0; nt < 8; nt++)
            #pragma unroll
            for (int q = 0; q < 4; q++) acc[mt][nt][q] = 0.f;

    auto issueX = [&](int ck, uint32_t stoff) {
        int c0 = ck * 64;
        #pragma unroll
        for (int l = 0; l < 5; l++) {
            int i = tid + l * 256;
            if (l < 4 || i < 1040) {
                int row = i >> 3, q = i & 7;
                int t = T0 - 2 + row;
                bool ok = (t >= 0);
                size_t g = ((size_t)(b * Tn + (ok ? t : 0))) * Dn + c0 + q * 8;
                cp16(sb + stoff + row * PX + q * 16, x + g, ok);
            }
        }
        CP_COMMIT();
    };

    issueX(0, S_X0);

    for (int ck = 0; ck < NCHUNK; ck++) {
        if (ck) __syncthreads();     // prev compute done: W + other X buffer free
        if (ck + 1 < NCHUNK) issueX(ck + 1, ((ck + 1) & 1) ? S_X1 : S_X0);

        // ---- W tile (sync): 3 taps x 128 o x 64 ch ----
        int c0 = ck * 64;
        #pragma unroll
        for (int l = 0; l < 12; l++) {
            int i = tid + l * 256;
            int row = i >> 3, q = i & 7;       // row 0..383
            int tap = row >> 7, o = row & 127;
            size_t g = ((size_t)(tap * Dn + N0 + o)) * Dn + c0 + q * 8;
            *(uint4*)(sm + S_W + tap * (128 * PX) + o * PX + q * 16) =
                *(const uint4*)(wsel + g);
        }
        if (ck + 1 < NCHUNK) asm volatile("cp.async.wait_group 1;" ::: "memory");
        else                 asm volatile("cp.async.wait_group 0;" ::: "memory");
        __syncthreads();

        uint32_t xbase = sb + ((ck & 1) ? S_X1 : S_X0);
        #pragma unroll
        for (int k16 = 0; k16 < 4; k16++) {
            int kb = k16 * 32 + ((lane >> 4) << 4);
            #pragma unroll
            for (int tap = 0; tap < 3; tap++) {
                uint32_t aoff = (uint32_t)((wm * 32 + (lane & 15) + tap) * PX) + kb;
                uint32_t boff = (uint32_t)(tap * (128 * PX) + (wn * 64 + (lane & 15)) * PX) + kb;
                uint32_t a0[4], a1[4];
                ldsm4(a0, xbase + aoff);
                ldsm4(a1, xbase + aoff + 16 * PX);
                uint32_t bw[4][4];
                #pragma unroll
                for (int q = 0; q < 4; q++)
                    ldsm4(bw[q], sb + S_W + boff + q * (16 * PX));
                #pragma unroll
                for (int nt = 0; nt < 8; nt++) {
                    uint32_t b2[2] = { bw[nt >> 1][nt & 1], bw[nt >> 1][(nt & 1) + 2] };
                    mma16816(acc[0][nt], a0, b2);
                    mma16816(acc[1][nt], a1, b2);
                }
            }
        }
    }

    // ---- epilogue: + bias, exact GELU, store fp16 ----
    __half* __restrict__ yout = (MODE == 1) ? g_h : g_y;
    int col0 = N0 + wn * 64 + (lane & 3) * 2;
    #pragma unroll
    for (int mt = 0; mt < 2; mt++) {
        int r0 = tile * 128 + wm * 32 + mt * 16 + (lane >> 2);
        #pragma unroll
        for (int nt = 0; nt < 8; nt++) {
            int col = col0 + nt * 8;
            float2 bi = *(const float2*)&bias[col];
            #pragma unroll
            for (int h = 0; h < 2; h++) {
                int r = r0 + h * 8;
                float v0 = gelu_exact(acc[mt][nt][2 * h + 0] + bi.x);
                float v1 = gelu_exact(acc[mt][nt][2 * h + 1] + bi.y);
                __half2 p;
                p.x = __float2half_rn(v0);
                p.y = __float2half_rn(v1);
                *(__half2*)&yout[(size_t)r * Dn + col] = p;
            }
        }
    }
}

// ============================================================================
// K4: LayerNorm over D=512 (+gamma/beta, *mask) fused with pooling partials.
// 8 rows per block (R11 config).
// ============================================================================
__global__ __launch_bounds__(256) void ln_pool_kernel(
    const float* __restrict__ g, const float* __restrict__ bb,
    const float* __restrict__ mask)
{
    __shared__ float part[8][1024];   // 32 KB
    int wid = threadIdx.x >> 5;
    int lane = threadIdx.x & 31;
    int row = blockIdx.x * 8 + wid;
    const __half* xr = g_h + (size_t)row * Dn;

    float4 v[4];
    float sum = 0.f;
    #pragma unroll
    for (int p = 0; p < 4; p++) {
        int c = p * 32 + lane;
        uint2 raw = *(const uint2*)(xr + 4 * c);
        __half2 h0 = *(__half2*)&raw.x;
        __half2 h1 = *(__half2*)&raw.y;
        float2 f0 = __half22float2(h0);
        float2 f1 = __half22float2(h1);
        v[p] = make_float4(f0.x, f0.y, f1.x, f1.y);
        sum += v[p].x + v[p].y + v[p].z + v[p].w;
    }
    #pragma unroll
    for (int o = 16; o; o >>= 1) sum += __shfl_xor_sync(0xffffffffu, sum, o);
    float mean = sum * (1.0f / Dn);

    float s2 = 0.f;
    #pragma unroll
    for (int p = 0; p < 4; p++) {
        float dx = v[p].x - mean, dy = v[p].y - mean, dz = v[p].z - mean, dw = v[p].w - mean;
        s2 += dx * dx + dy * dy + dz * dz + dw * dw;
    }
    #pragma unroll
    for (int o = 16; o; o >>= 1) s2 += __shfl_xor_sync(0xffffffffu, s2, o);
    float rstd = rsqrtf(s2 * (1.0f / Dn) + 1e-5f);

    float m = fminf(fmaxf(mask[row], 0.f), 1.f);
    #pragma unroll
    for (int p = 0; p < 4; p++) {
        int c = p * 32 + lane;
        float4 gg = ((const float4*)g)[c];
        float4 bv = ((const float4*)bb)[c];
        float o0 = ((v[p].x - mean) * rstd * gg.x + bv.x) * m;
        float o1 = ((v[p].y - mean) * rstd * gg.y + bv.y) * m;
        float o2 = ((v[p].z - mean) * rstd * gg.z + bv.z) * m;
        float o3 = ((v[p].w - mean) * rstd * gg.w + bv.w) * m;
        int d = 4 * c;
        part[wid][d + 0] = o0;
        part[wid][d + 1] = o1;
        part[wid][d + 2] = o2;
        part[wid][d + 3] = o3;
        part[wid][512 + d + 0] = o0 * o0;
        part[wid][512 + d + 1] = o1 * o1;
        part[wid][512 + d + 2] = o2 * o2;
        part[wid][512 + d + 3] = o3 * o3;
    }
    __syncthreads();

    float* dst = g_part + (size_t)blockIdx.x * 1024;
    for (int i = threadIdx.x; i < 1024; i += 256) {
        float s = 0.f;
        #pragma unroll
        for (int w = 0; w < 8; w++) s += part[w][i];
        dst[i] = s;
    }
}

// ============================================================================
// K5: finalize pooling: reduce 256 partials per batch -> g_cat [B, 2D]
// ============================================================================
__global__ __launch_bounds__(128) void pool_finalize_kernel()
{
    int b = blockIdx.x;
    int d = blockIdx.y * 128 + threadIdx.x;   // 0..511
    const float* pb = g_part + (size_t)b * 256 * 1024;
    float sv = 0.f, sq = 0.f;
    #pragma unroll 4
    for (int s = 0; s < 256; s++) {
        sv += pb[(size_t)s * 1024 + d];
        sq += pb[(size_t)s * 1024 + 512 + d];
    }
    float n = g_n[b];
    float denom = fmaxf(n, 1.f);
    float mean = sv / denom;
    float diff2 = sq - 2.f * mean * sv + mean * mean * n;
    float sd = sqrtf(fmaxf(diff2, 0.f) / denom + 1e-6f);
    g_cat[b * 2 * Dn + d] = mean;
    g_cat[b * 2 * Dn + Dn + d] = sd;
}

// ============================================================================
// K6: p1 (1024 -> 512) + gelu -> g_g1
// ============================================================================
__global__ __launch_bounds__(128) void mlp1_kernel(
    const float* __restrict__ w, const float* __restrict__ bias)
{
    __shared__ float c[2 * Dn];
    int b = blockIdx.x;
    int j = blockIdx.y * 128 + threadIdx.x;
    for (int i = threadIdx.x; i < 2 * Dn; i += 128) c[i] = g_cat[b * 2 * Dn + i];
    __syncthreads();
    const float* wr = w + (size_t)j * (2 * Dn);
    float acc = bias[j];
    #pragma unroll 8
    for (int k = 0; k < 2 * Dn; k++) acc = fmaf(c[k], wr[k], acc);
    g_g1[b * Dn + j] = gelu_exact(acc);
}

// ============================================================================
// K7: p2 (512 -> 512) + tanh + support zero-guard -> summary_state out
// ============================================================================
__global__ __launch_bounds__(128) void mlp2_kernel(
    const float* __restrict__ w, const float* __restrict__ bias,
    float* __restrict__ out)
{
    __shared__ float c[Dn];
    int b = blockIdx.x;
    int j = blockIdx.y * 128 + threadIdx.x;
    for (int i = threadIdx.x; i < Dn; i += 128) c[i] = g_g1[b * Dn + i];
    __syncthreads();
    const float* wr = w + (size_t)j * Dn;
    float acc = bias[j];
    #pragma unroll 8
    for (int k = 0; k < Dn; k++) acc = fmaf(c[k], wr[k], acc);
    float v = tanhf(acc);
    if (g_n[b] <= 0.f) v = 0.f;
    out[O_SUM + b * Dn + j] = v;
}

// ============================================================================
// K8: coeff_norm = ||summary_state||_2 per batch
// ============================================================================
__global__ __launch_bounds__(128) void norm_kernel(float* __restrict__ out)
{
    __shared__ float red[32];
    int b = blockIdx.x;
    float s = 0.f;
    for (int i = threadIdx.x; i < Dn; i += 128) {
        float v = out[O_SUM + b * Dn + i];
        s += v * v;
    }
    float tot = blkReduceSum(s, red);
    if (threadIdx.x == 0) out[O_NORM + b] = sqrtf(tot);
}

// ============================================================================
extern "C" void kernel_launch(void* const* d_in, const int* in_sizes, int n_in,
                              void* d_out, int out_size)
{
    const int*   ids  = (const int*)d_in[0];
    const float* dur  = (const float*)d_in[1];
    const float* mask = (const float*)d_in[2];
    const float* emb  = (const float*)d_in[3];
    const float* auxw = (const float*)d_in[4];
    const float* auxb = (const float*)d_in[5];
    const float* c1w  = (const float*)d_in[6];
    const float* c1b  = (const float*)d_in[7];
    const float* c2w  = (const float*)d_in[8];
    const float* c2b  = (const float*)d_in[9];
    const float* lng  = (const float*)d_in[10];
    const float* lnb  = (const float*)d_in[11];
    const float* p1w  = (const float*)d_in[12];
    const float* p1b  = (const float*)d_in[13];
    const float* p2w  = (const float*)d_in[14];
    const float* p2b  = (const float*)d_in[15];
    float* out = (float*)d_out;

    cudaFuncSetAttribute(conv_mma_kernel<0, 0>,
                         cudaFuncAttributeMaxDynamicSharedMemorySize, CONV_SMEM);
    cudaFuncSetAttribute(conv_mma_kernel<1, 1>,
                         cudaFuncAttributeMaxDynamicSharedMemorySize, CONV_SMEM);

    stats_kernel<<<Bn, 1024>>>(dur, mask, out);
    prep_w_kernel<<<(2 * 3 * Dn * Dn) / 256, 256>>>(c1w, c2w);
    embed_kernel<<<NT, 128>>>(ids, emb, auxw, auxb);

    dim3 cg(Dn / 128, NT / 128);   // (4, 512)
    conv_mma_kernel<0, 0><<<cg, 256, CONV_SMEM>>>(c1b);
    conv_mma_kernel<1, 1><<<cg, 256, CONV_SMEM>>>(c2b);

    ln_pool_kernel<<<NT / 8, 256>>>(lng, lnb, mask);

    dim3 pf(Bn, Dn / 128);         // (32, 4)
    pool_finalize_kernel<<<pf, 128>>>();

    dim3 mg(Bn, Dn / 128);
    mlp1_kernel<<<mg, 128>>>(p1w, p1b);
    mlp2_kernel<<<mg, 128>>>(p2w, p2b, out);
    norm_kernel<<<Bn, 128>>>(out);
}

// round 16
// speedup vs baseline: 1.3064x; 1.0272x over previous
#include <cuda_runtime.h>
#include <cuda_bf16.h>
#include <cuda_fp16.h>
#include <math.h>
#include <stdint.h>

#define Bn 32
#define Tn 2048
#define Dn 512
#define Vn 1024
#define NT 65536          // Bn*Tn rows

// ---- output offsets (floats), tuple order flattened ----
#define O_GR     0
#define O_SUM    32
#define O_RMEAN  16416
#define O_RVAR   16448
#define O_COV    16480
#define O_MASK   16512
#define O_LOGDUR 82048
#define O_REF    147584
#define O_ATTN   213120
#define O_FIT    278656
#define O_NORM   344192

// ---- scratch (device globals; no runtime allocation) ----
__device__ __half g_x[(size_t)NT * Dn];    // 64 MB  conv1 input fp16
__device__ __half g_y[(size_t)NT * Dn];    // 64 MB  conv1 out fp16
__device__ __half g_h[(size_t)NT * Dn];    // 64 MB  conv2 out fp16
__device__ __half g_w1[(size_t)3 * Dn * Dn];  // conv1 weights fp16 [tap][o][c]
__device__ __half g_w2[(size_t)3 * Dn * Dn];  // conv2 weights fp16
__device__ float g_part[(size_t)(NT / 16) * 1024];  // 16 MB pool partials
__device__ float g_ref[NT];
__device__ float g_cat[Bn * 2 * Dn];
__device__ float g_g1[Bn * Dn];
__device__ float g_n[Bn];

__device__ __forceinline__ float gelu_exact(float x) {
    return 0.5f * x * (1.0f + erff(x * 0.70710678118654752440f));
}

__device__ __forceinline__ uint32_t smem_u32(const void* p) {
    uint32_t a;
    asm("{ .reg .u64 t; cvta.to.shared.u64 t, %1; cvt.u32.u64 %0, t; }" : "=r"(a) : "l"(p));
    return a;
}

__device__ __forceinline__ void ldsm4(uint32_t* r, uint32_t addr) {
    asm volatile("ldmatrix.sync.aligned.m8n8.x4.shared.b16 {%0,%1,%2,%3}, [%4];"
        : "=r"(r[0]), "=r"(r[1]), "=r"(r[2]), "=r"(r[3]) : "r"(addr));
}

__device__ __forceinline__ void mma16816(float* d, const uint32_t* a, const uint32_t* b) {
    asm volatile(
        "mma.sync.aligned.m16n8k16.row.col.f32.f16.f16.f32 "
        "{%0,%1,%2,%3}, {%4,%5,%6,%7}, {%8,%9}, {%0,%1,%2,%3};"
        : "+f"(d[0]), "+f"(d[1]), "+f"(d[2]), "+f"(d[3])
        : "r"(a[0]), "r"(a[1]), "r"(a[2]), "r"(a[3]), "r"(b[0]), "r"(b[1]));
}

__device__ __forceinline__ void cp16(uint32_t dst, const void* src, bool pred) {
    int sz = pred ? 16 : 0;
    asm volatile("cp.async.cg.shared.global [%0], [%1], 16, %2;"
        :: "r"(dst), "l"(src), "r"(sz) : "memory");
}
#define CP_COMMIT() asm volatile("cp.async.commit_group;" ::: "memory")

// works for blockDim.x multiple of 32, <= 1024
__device__ __forceinline__ float blkReduceSum(float v, float* red) {
    int tid = threadIdx.x;
    int lane = tid & 31, wid = tid >> 5;
    #pragma unroll
    for (int o = 16; o; o >>= 1) v += __shfl_xor_sync(0xffffffffu, v, o);
    if (lane == 0) red[wid] = v;
    __syncthreads();
    float r = 0.f;
    if (wid == 0) {
        int nw = blockDim.x >> 5;
        r = (lane < nw) ? red[lane] : 0.f;
        #pragma unroll
        for (int o = 16; o; o >>= 1) r += __shfl_xor_sync(0xffffffffu, r, o);
        if (lane == 0) red[0] = r;
    }
    __syncthreads();
    r = red[0];
    __syncthreads();
    return r;
}

// ============================================================================
// K0: per-batch stats (logdur, exact median via bitonic sort, residual stats)
// Full __syncthreads in every bitonic phase (deterministic; do not relax).
// ============================================================================
__global__ __launch_bounds__(1024) void stats_kernel(
    const float* __restrict__ dur, const float* __restrict__ mask,
    float* __restrict__ out)
{
    __shared__ float s[Tn];
    __shared__ float red[32];
    int b = blockIdx.x;
    int tid = threadIdx.x;
    const float* durb = dur + b * Tn;
    const float* mb   = mask + b * Tn;

    float ldv[2], mval[2];
    int cnt = 0;
    #pragma unroll
    for (int p = 0; p < 2; p++) {
        int i = tid + p * 1024;
        float m = fminf(fmaxf(mb[i], 0.f), 1.f);
        float ld = logf(fmaxf(durb[i], 1e-4f)) * m;
        mval[p] = m;
        ldv[p] = ld;
        bool valid = m > 0.5f;
        s[i] = valid ? ld : __int_as_float(0x7f800000);
        if (valid) cnt++;
    }
    float n_f = blkReduceSum((float)cnt, red);
    int n = (int)(n_f + 0.5f);

    for (int k = 2; k <= Tn; k <<= 1) {
        for (int j = k >> 1; j > 0; j >>= 1) {
            #pragma unroll
            for (int p = 0; p < 2; p++) {
                int i = tid + p * 1024;
                int ixj = i ^ j;
                if (ixj > i) {
                    bool up = ((i & k) == 0);
                    float a = s[i], c = s[ixj];
                    bool swap = up ? (a > c) : (a < c);
                    if (swap) { s[i] = c; s[ixj] = a; }
                }
            }
            __syncthreads();
        }
    }

    float med = (n > 0) ? s[(n - 1) >> 1] : 0.f;
    float support = fmaxf(n_f, 1.f);

    float refv[2];
    float sum_ref = 0.f;
    #pragma unroll
    for (int p = 0; p < 2; p++) {
        float r = (ldv[p] - med) * mval[p];
        refv[p] = r;
        sum_ref += r * mval[p];
    }
    float tot = blkReduceSum(sum_ref, red);
    float rmean = tot / support;

    float sv = 0.f;
    #pragma unroll
    for (int p = 0; p < 2; p++) {
        float d = refv[p] - rmean;
        sv += d * d * mval[p];
    }
    float totv = blkReduceSum(sv, red);
    float rvar = fmaxf(totv / support, 1e-4f);

    #pragma unroll
    for (int p = 0; p < 2; p++) {
        int i = tid + p * 1024;
        int gi = b * Tn + i;
        out[O_MASK   + gi] = mval[p];
        out[O_LOGDUR + gi] = ldv[p];
        out[O_REF    + gi] = refv[p];
        out[O_ATTN   + gi] = mval[p] / support;
        out[O_FIT    + gi] = rmean * mval[p];
        g_ref[gi] = refv[p];
    }
    if (tid == 0) {
        out[O_GR    + b] = med;
        out[O_RMEAN + b] = rmean;
        out[O_RVAR  + b] = rvar;
        out[O_COV   + b] = fmaxf(n_f / (float)Tn, 0.05f);
        g_n[b] = n_f;
    }
}

// ============================================================================
// K1: embedding + residual projection -> fp16 (g_x)
// ============================================================================
__global__ __launch_bounds__(128) void embed_kernel(
    const int* __restrict__ ids, const float* __restrict__ emb,
    const float* __restrict__ auxw, const float* __restrict__ auxb)
{
    int row = blockIdx.x;
    int tid = threadIdx.x;
    int id = ids[row];
    float r = g_ref[row];
    float4 e = ((const float4*)(emb + (size_t)id * Dn))[tid];
    float4 w = ((const float4*)auxw)[tid];
    float4 bb = ((const float4*)auxb)[tid];
    __half h[4];
    h[0] = __float2half_rn(e.x + r * w.x + bb.x);
    h[1] = __float2half_rn(e.y + r * w.y + bb.y);
    h[2] = __float2half_rn(e.z + r * w.z + bb.z);
    h[3] = __float2half_rn(e.w + r * w.w + bb.w);
    *(ushort4*)(g_x + (size_t)row * Dn + tid * 4) = *(ushort4*)h;
}

// ============================================================================
// K2: weight prep for BOTH convs: Wt[k][o][c] = w[o][c][k] in fp16
// ============================================================================
__global__ __launch_bounds__(256) void prep_w_kernel(
    const float* __restrict__ w1, const float* __restrict__ w2)
{
    int idx = blockIdx.x * 256 + threadIdx.x;   // over 2 * 786432
    int half_sel = idx >= (3 * Dn * Dn);
    int i = idx - half_sel * (3 * Dn * Dn);
    int j = i >> 9;           // tap*512 + o
    int c = i & 511;
    int k = j >> 9;
    int o = j & 511;
    const float* w = half_sel ? w2 : w1;
    __half v = __float2half_rn(w[((size_t)o * Dn + c) * 3 + k]);
    if (half_sel) g_w2[i] = v;
    else          g_w1[i] = v;
}

// ============================================================================
// K3: causal conv via mma.sync fp16 (R11 config: 256 thr, 2 CTAs/SM,
// warp tile 32x64 (4m x 2n), CTA tile 128x128, K-chunk 64, X cp.async
// double-buffered, W sync-loaded).
// ============================================================================
#define PX 144                       // smem row pitch (bytes): 128B data + 16 pad
#define XSTAGE (130 * PX)            // 18720
#define S_X0 0
#define S_X1 XSTAGE
#define S_W  (2 * XSTAGE)            // 37440
#define CONV_SMEM (S_W + 3 * 128 * PX)  // 92736
#define NCHUNK 8

template<int SRC, int MODE>
__global__ __launch_bounds__(256, 2) void conv_mma_kernel(const float* __restrict__ bias)
{
    extern __shared__ char sm[];
    const __half* __restrict__ x = (SRC == 0) ? g_x : g_y;
    const __half* __restrict__ wsel = (SRC == 0) ? g_w1 : g_w2;

    uint32_t sb = smem_u32(sm);
    int tid = threadIdx.x;
    int lane = tid & 31, wid = tid >> 5;
    int wm = wid & 3;              // 0..3, 32 rows each
    int wn = wid >> 2;             // 0..1, 64 cols each

    int N0 = blockIdx.x * 128;     // output-channel tile
    int tile = blockIdx.y;         // global row tile (128 rows)
    int b  = tile >> 4;
    int T0 = (tile & 15) << 7;

    float acc[2][8][4];
    #pragma unroll
    for (int mt = 0; mt < 2; mt++)
        #pragma unroll
        for (int nt = 0; nt < 8; nt++)
            #pragma unroll
            for (int q = 0; q < 4; q++) acc[mt][nt][q] = 0.f;

    auto issueX = [&](int ck, uint32_t stoff) {
        int c0 = ck * 64;
        #pragma unroll
        for (int l = 0; l < 5; l++) {
            int i = tid + l * 256;
            if (l < 4 || i < 1040) {
                int row = i >> 3, q = i & 7;
                int t = T0 - 2 + row;
                bool ok = (t >= 0);
                size_t g = ((size_t)(b * Tn + (ok ? t : 0))) * Dn + c0 + q * 8;
                cp16(sb + stoff + row * PX + q * 16, x + g, ok);
            }
        }
        CP_COMMIT();
    };

    issueX(0, S_X0);

    for (int ck = 0; ck < NCHUNK; ck++) {
        if (ck) __syncthreads();     // prev compute done: W + other X buffer free
        if (ck + 1 < NCHUNK) issueX(ck + 1, ((ck + 1) & 1) ? S_X1 : S_X0);

        // ---- W tile (sync): 3 taps x 128 o x 64 ch ----
        int c0 = ck * 64;
        #pragma unroll
        for (int l = 0; l < 12; l++) {
            int i = tid + l * 256;
            int row = i >> 3, q = i & 7;       // row 0..383
            int tap = row >> 7, o = row & 127;
            size_t g = ((size_t)(tap * Dn + N0 + o)) * Dn + c0 + q * 8;
            *(uint4*)(sm + S_W + tap * (128 * PX) + o * PX + q * 16) =
                *(const uint4*)(wsel + g);
        }
        if (ck + 1 < NCHUNK) asm volatile("cp.async.wait_group 1;" ::: "memory");
        else                 asm volatile("cp.async.wait_group 0;" ::: "memory");
        __syncthreads();

        uint32_t xbase = sb + ((ck & 1) ? S_X1 : S_X0);
        #pragma unroll
        for (int k16 = 0; k16 < 4; k16++) {
            int kb = k16 * 32 + ((lane >> 4) << 4);
            #pragma unroll
            for (int tap = 0; tap < 3; tap++) {
                uint32_t aoff = (uint32_t)((wm * 32 + (lane & 15) + tap) * PX) + kb;
                uint32_t boff = (uint32_t)(tap * (128 * PX) + (wn * 64 + (lane & 15)) * PX) + kb;
                uint32_t a0[4], a1[4];
                ldsm4(a0, xbase + aoff);
                ldsm4(a1, xbase + aoff + 16 * PX);
                uint32_t bw[4][4];
                #pragma unroll
                for (int q = 0; q < 4; q++)
                    ldsm4(bw[q], sb + S_W + boff + q * (16 * PX));
                #pragma unroll
                for (int nt = 0; nt < 8; nt++) {
                    uint32_t b2[2] = { bw[nt >> 1][nt & 1], bw[nt >> 1][(nt & 1) + 2] };
                    mma16816(acc[0][nt], a0, b2);
                    mma16816(acc[1][nt], a1, b2);
                }
            }
        }
    }

    // ---- epilogue: + bias, exact GELU, store fp16 ----
    __half* __restrict__ yout = (MODE == 1) ? g_h : g_y;
    int col0 = N0 + wn * 64 + (lane & 3) * 2;
    #pragma unroll
    for (int mt = 0; mt < 2; mt++) {
        int r0 = tile * 128 + wm * 32 + mt * 16 + (lane >> 2);
        #pragma unroll
        for (int nt = 0; nt < 8; nt++) {
            int col = col0 + nt * 8;
            float2 bi = *(const float2*)&bias[col];
            #pragma unroll
            for (int h = 0; h < 2; h++) {
                int r = r0 + h * 8;
                float v0 = gelu_exact(acc[mt][nt][2 * h + 0] + bi.x);
                float v1 = gelu_exact(acc[mt][nt][2 * h + 1] + bi.y);
                __half2 p;
                p.x = __float2half_rn(v0);
                p.y = __float2half_rn(v1);
                *(__half2*)&yout[(size_t)r * Dn + col] = p;
            }
        }
    }
}

// ============================================================================
// K4: LayerNorm over D=512 (+gamma/beta, *mask) fused with pooling partials.
// 512 threads, 16 rows per block, 64 KB dynamic smem (3 blocks/SM).
// Per-warp math identical to the proven 8-row version; only the block shape
// and the 16-way final tree differ.
// ============================================================================
#define LNP_SMEM (16 * 1024 * 4)   // 65536 bytes

__global__ __launch_bounds__(512) void ln_pool_kernel(
    const float* __restrict__ g, const float* __restrict__ bb,
    const float* __restrict__ mask)
{
    extern __shared__ float part_raw[];
    float (*part)[1024] = (float(*)[1024])part_raw;
    int wid = threadIdx.x >> 5;
    int lane = threadIdx.x & 31;
    int row = blockIdx.x * 16 + wid;
    const __half* xr = g_h + (size_t)row * Dn;

    float4 v[4];
    float sum = 0.f;
    #pragma unroll
    for (int p = 0; p < 4; p++) {
        int c = p * 32 + lane;
        uint2 raw = *(const uint2*)(xr + 4 * c);
        __half2 h0 = *(__half2*)&raw.x;
        __half2 h1 = *(__half2*)&raw.y;
        float2 f0 = __half22float2(h0);
        float2 f1 = __half22float2(h1);
        v[p] = make_float4(f0.x, f0.y, f1.x, f1.y);
        sum += v[p].x + v[p].y + v[p].z + v[p].w;
    }
    #pragma unroll
    for (int o = 16; o; o >>= 1) sum += __shfl_xor_sync(0xffffffffu, sum, o);
    float mean = sum * (1.0f / Dn);

    float s2 = 0.f;
    #pragma unroll
    for (int p = 0; p < 4; p++) {
        float dx = v[p].x - mean, dy = v[p].y - mean, dz = v[p].z - mean, dw = v[p].w - mean;
        s2 += dx * dx + dy * dy + dz * dz + dw * dw;
    }
    #pragma unroll
    for (int o = 16; o; o >>= 1) s2 += __shfl_xor_sync(0xffffffffu, s2, o);
    float rstd = rsqrtf(s2 * (1.0f / Dn) + 1e-5f);

    float m = fminf(fmaxf(mask[row], 0.f), 1.f);
    #pragma unroll
    for (int p = 0; p < 4; p++) {
        int c = p * 32 + lane;
        float4 gg = ((const float4*)g)[c];
        float4 bv = ((const float4*)bb)[c];
        float o0 = ((v[p].x - mean) * rstd * gg.x + bv.x) * m;
        float o1 = ((v[p].y - mean) * rstd * gg.y + bv.y) * m;
        float o2 = ((v[p].z - mean) * rstd * gg.z + bv.z) * m;
        float o3 = ((v[p].w - mean) * rstd * gg.w + bv.w) * m;
        int d = 4 * c;
        part[wid][d + 0] = o0;
        part[wid][d + 1] = o1;
        part[wid][d + 2] = o2;
        part[wid][d + 3] = o3;
        part[wid][512 + d + 0] = o0 * o0;
        part[wid][512 + d + 1] = o1 * o1;
        part[wid][512 + d + 2] = o2 * o2;
        part[wid][512 + d + 3] = o3 * o3;
    }
    __syncthreads();

    float* dst = g_part + (size_t)blockIdx.x * 1024;
    for (int i = threadIdx.x; i < 1024; i += 512) {
        float s = 0.f;
        #pragma unroll
        for (int w = 0; w < 16; w++) s += part[w][i];
        dst[i] = s;
    }
}

// ============================================================================
// K5: finalize pooling: reduce 128 partials per batch -> g_cat [B, 2D]
// ============================================================================
__global__ __launch_bounds__(128) void pool_finalize_kernel()
{
    int b = blockIdx.x;
    int d = blockIdx.y * 128 + threadIdx.x;   // 0..511
    const float* pb = g_part + (size_t)b * 128 * 1024;
    float sv = 0.f, sq = 0.f;
    #pragma unroll 4
    for (int s = 0; s < 128; s++) {
        sv += pb[(size_t)s * 1024 + d];
        sq += pb[(size_t)s * 1024 + 512 + d];
    }
    float n = g_n[b];
    float denom = fmaxf(n, 1.f);
    float mean = sv / denom;
    float diff2 = sq - 2.f * mean * sv + mean * mean * n;
    float sd = sqrtf(fmaxf(diff2, 0.f) / denom + 1e-6f);
    g_cat[b * 2 * Dn + d] = mean;
    g_cat[b * 2 * Dn + Dn + d] = sd;
}

// ============================================================================
// K6: p1 (1024 -> 512) + gelu -> g_g1
// ============================================================================
__global__ __launch_bounds__(128) void mlp1_kernel(
    const float* __restrict__ w, const float* __restrict__ bias)
{
    __shared__ float c[2 * Dn];
    int b = blockIdx.x;
    int j = blockIdx.y * 128 + threadIdx.x;
    for (int i = threadIdx.x; i < 2 * Dn; i += 128) c[i] = g_cat[b * 2 * Dn + i];
    __syncthreads();
    const float* wr = w + (size_t)j * (2 * Dn);
    float acc = bias[j];
    #pragma unroll 8
    for (int k = 0; k < 2 * Dn; k++) acc = fmaf(c[k], wr[k], acc);
    g_g1[b * Dn + j] = gelu_exact(acc);
}

// ============================================================================
// K7: p2 (512 -> 512) + tanh + support zero-guard -> summary_state out
// ============================================================================
__global__ __launch_bounds__(128) void mlp2_kernel(
    const float* __restrict__ w, const float* __restrict__ bias,
    float* __restrict__ out)
{
    __shared__ float c[Dn];
    int b = blockIdx.x;
    int j = blockIdx.y * 128 + threadIdx.x;
    for (int i = threadIdx.x; i < Dn; i += 128) c[i] = g_g1[b * Dn + i];
    __syncthreads();
    const float* wr = w + (size_t)j * Dn;
    float acc = bias[j];
    #pragma unroll 8
    for (int k = 0; k < Dn; k++) acc = fmaf(c[k], wr[k], acc);
    float v = tanhf(acc);
    if (g_n[b] <= 0.f) v = 0.f;
    out[O_SUM + b * Dn + j] = v;
}

// ============================================================================
// K8: coeff_norm = ||summary_state||_2 per batch
// ============================================================================
__global__ __launch_bounds__(128) void norm_kernel(float* __restrict__ out)
{
    __shared__ float red[32];
    int b = blockIdx.x;
    float s = 0.f;
    for (int i = threadIdx.x; i < Dn; i += 128) {
        float v = out[O_SUM + b * Dn + i];
        s += v * v;
    }
    float tot = blkReduceSum(s, red);
    if (threadIdx.x == 0) out[O_NORM + b] = sqrtf(tot);
}

// ============================================================================
extern "C" void kernel_launch(void* const* d_in, const int* in_sizes, int n_in,
                              void* d_out, int out_size)
{
    const int*   ids  = (const int*)d_in[0];
    const float* dur  = (const float*)d_in[1];
    const float* mask = (const float*)d_in[2];
    const float* emb  = (const float*)d_in[3];
    const float* auxw = (const float*)d_in[4];
    const float* auxb = (const float*)d_in[5];
    const float* c1w  = (const float*)d_in[6];
    const float* c1b  = (const float*)d_in[7];
    const float* c2w  = (const float*)d_in[8];
    const float* c2b  = (const float*)d_in[9];
    const float* lng  = (const float*)d_in[10];
    const float* lnb  = (const float*)d_in[11];
    const float* p1w  = (const float*)d_in[12];
    const float* p1b  = (const float*)d_in[13];
    const float* p2w  = (const float*)d_in[14];
    const float* p2b  = (const float*)d_in[15];
    float* out = (float*)d_out;

    cudaFuncSetAttribute(conv_mma_kernel<0, 0>,
                         cudaFuncAttributeMaxDynamicSharedMemorySize, CONV_SMEM);
    cudaFuncSetAttribute(conv_mma_kernel<1, 1>,
                         cudaFuncAttributeMaxDynamicSharedMemorySize, CONV_SMEM);
    cudaFuncSetAttribute(ln_pool_kernel,
                         cudaFuncAttributeMaxDynamicSharedMemorySize, LNP_SMEM);

    stats_kernel<<<Bn, 1024>>>(dur, mask, out);
    prep_w_kernel<<<(2 * 3 * Dn * Dn) / 256, 256>>>(c1w, c2w);
    embed_kernel<<<NT, 128>>>(ids, emb, auxw, auxb);

    dim3 cg(Dn / 128, NT / 128);   // (4, 512)
    conv_mma_kernel<0, 0><<<cg, 256, CONV_SMEM>>>(c1b);
    conv_mma_kernel<1, 1><<<cg, 256, CONV_SMEM>>>(c2b);

    ln_pool_kernel<<<NT / 16, 512, LNP_SMEM>>>(lng, lnb, mask);

    dim3 pf(Bn, Dn / 128);         // (32, 4)
    pool_finalize_kernel<<<pf, 128>>>();

    dim3 mg(Bn, Dn / 128);
    mlp1_kernel<<<mg, 128>>>(p1w, p1b);
    mlp2_kernel<<<mg, 128>>>(p2w, p2b, out);
    norm_kernel<<<Bn, 128>>>(out);
}